// round 9
// baseline (speedup 1.0000x reference)
#include <cuda_runtime.h>
#include <cstdint>
#include <math.h>

// IMDCT, symmetry-halved GEMM, round 9: 8-warp blocks, 5-pair windows, 16 warps/SM.
//
// z_col[j] = sum_f kr[j][f]*spec[b,f,col],  kr[j][f] = kernels[128+j][f]/(128*win[128+j])
//   out[b, s*256+k] = win[k]    *(k<128 ? -z_s[127-k]     : z_s[k-128])
//                   + win[k+256]*(k<128 ?  z_{s-1}[k+128] : z_{s-1}[383-k])
//
// Block = 256 threads = 8 warps, NSEG=64 segments; spec tile 66 cols (s0-1..s0+64).
// Warp w owns cols 8w..8w+9 (5 packed pairs) covering segs 8w..8w+7. Lane owns 8
// z-rows t = lane+32m. Inner loop m-major: 5 hoisted LDS.b64 then per-m PACK2 + 5
// FMA2 -> acc 80 regs, ~118 total, 2 blocks/SM = 16 warps. Overlap cols across
// warps are recomputed bit-identically (same f-order/weights/spec) - benign.

#define NFREQ    256
#define TFRAMES  4096
#define NSEG     64
#define NCOLS    66
#define SSTR     68         // spec tile row stride (words)
#define LOUT     1048832
#define DSTR     260        // Dt row stride (words)
#define SMBYTES  (NFREQ * SSTR * 4)   // 69,632 (Dt needs 66*260*4 = 68,640 <= this)

#define FMA2(acc, a, v) \
    asm("fma.rn.f32x2 %0, %1, %2, %0;" : "+l"(acc) : "l"(a), "l"(v))
#define PACK2(dst, x) \
    asm("mov.b64 %0, {%1, %1};" : "=l"(dst) : "r"(__float_as_uint(x)))

// Reduced-basis weights (rows 128..383 -> t=0..255), pre-scaled by 1/(128*win):
//   g_w0[f*32+lane] = {kr(lane), kr(lane+32), kr(lane+64), kr(lane+96)}(f)
//   g_w1[f*32+lane] = {kr(lane+128), kr(lane+160), kr(lane+192), kr(lane+224)}(f)
// One pad f-row each for depth-1 prefetch overrun.
__device__ float4 g_w0[257 * 32];
__device__ float4 g_w1[257 * 32];
__device__ float  g_win[512];

static __device__ __forceinline__ float win_of(int t) {
    return sinf((float)M_PI * (float)(2 * t + 1) * (1.0f / 1024.0f));
}

__global__ void prep_kernel(const float* __restrict__ kernels)
{
    int idx = blockIdx.x * blockDim.x + threadIdx.x;   // 8192 threads
    if (idx < 512) g_win[idx] = win_of(idx);
    int lane = idx & 31;
    int f    = idx >> 5;                               // 0..255
    const float s = 1.0f / 128.0f;
    float4 w0, w1;
    w0.x = s * kernels[(128 + lane      ) * 256 + f] / win_of(128 + lane      );
    w0.y = s * kernels[(128 + lane +  32) * 256 + f] / win_of(128 + lane +  32);
    w0.z = s * kernels[(128 + lane +  64) * 256 + f] / win_of(128 + lane +  64);
    w0.w = s * kernels[(128 + lane +  96) * 256 + f] / win_of(128 + lane +  96);
    w1.x = s * kernels[(128 + lane + 128) * 256 + f] / win_of(128 + lane + 128);
    w1.y = s * kernels[(128 + lane + 160) * 256 + f] / win_of(128 + lane + 160);
    w1.z = s * kernels[(128 + lane + 192) * 256 + f] / win_of(128 + lane + 192);
    w1.w = s * kernels[(128 + lane + 224) * 256 + f] / win_of(128 + lane + 224);
    g_w0[f * 32 + lane] = w0;
    g_w1[f * 32 + lane] = w1;
}

__global__ __launch_bounds__(256, 2)
void imdct_main_kernel(const float* __restrict__ spec, float* __restrict__ out)
{
    extern __shared__ float sm[];                      // spec tile, reused as Dt

    const int tid  = threadIdx.x;                      // 0..255
    const int lane = tid & 31;
    const int w    = tid >> 5;                         // warp 0..7 -> col window 8w
    const int b    = blockIdx.y;
    const int s0   = blockIdx.x * NSEG;

    // ---- Stage spec cols c = s0-1 .. s0+64 (66 cols), zero-fill edges/pad ----
    const float* specB = spec + (size_t)b * NFREQ * TFRAMES;
    #pragma unroll 4
    for (int idx = tid; idx < NFREQ * SSTR; idx += 256) {
        int f = idx / SSTR;
        int j = idx - f * SSTR;
        int c = s0 - 1 + j;
        float v = 0.0f;
        if (j < NCOLS && c >= 0 && c < TFRAMES)
            v = __ldg(&specB[(size_t)f * TFRAMES + c]);
        sm[idx] = v;
    }
    __syncthreads();

    // ---- Accumulators: 8 rows x 5 col-pairs (window cols 8w .. 8w+9) ----
    unsigned long long acc[8][5];
    #pragma unroll
    for (int m = 0; m < 8; m++)
        #pragma unroll
        for (int p = 0; p < 5; p++) acc[m][p] = 0ull;

    const uint32_t sbase = (uint32_t)__cvta_generic_to_shared(sm) + (uint32_t)(8 * w * 4);
    const float4* __restrict__ w0p = g_w0 + lane;
    const float4* __restrict__ w1p = g_w1 + lane;

    float4 wc0 = w0p[0], wc1 = w1p[0];                 // depth-1 prefetch

    #pragma unroll 1
    for (int f = 0; f < NFREQ; f++) {
        float4 wn0 = w0p[(f + 1) * 32];
        float4 wn1 = w1p[(f + 1) * 32];

        uint32_t srow = sbase + (uint32_t)(f * (SSTR * 4));
        unsigned long long v[5];                       // hoisted spec col-pairs
        #pragma unroll
        for (int p = 0; p < 5; p++)
            asm volatile("ld.shared.b64 %0, [%1];" : "=l"(v[p]) : "r"(srow + p * 8));

        const float wv[8] = { wc0.x, wc0.y, wc0.z, wc0.w, wc1.x, wc1.y, wc1.z, wc1.w };
        #pragma unroll
        for (int m = 0; m < 8; m++) {
            unsigned long long w2;
            PACK2(w2, wv[m]);
            FMA2(acc[m][0], w2, v[0]);
            FMA2(acc[m][1], w2, v[1]);
            FMA2(acc[m][2], w2, v[2]);
            FMA2(acc[m][3], w2, v[3]);
            FMA2(acc[m][4], w2, v[4]);
        }

        wc0 = wn0; wc1 = wn1;
    }

    // ---- Stage Dt[col][j]: warp w stores cols 8w+2p (+1), j = lane+32m ----
    // (cols 8w+8, 8w+9 duplicated by warp w+1 with bit-identical values)
    __syncthreads();                                   // done reading spec from sm
    #pragma unroll
    for (int m = 0; m < 8; m++) {
        int j = lane + 32 * m;
        #pragma unroll
        for (int p = 0; p < 5; p++) {
            unsigned long long a = acc[m][p];
            sm[(8 * w + 2 * p)     * DSTR + j] = __uint_as_float((unsigned)a);
            sm[(8 * w + 2 * p + 1) * DSTR + j] = __uint_as_float((unsigned)(a >> 32));
        }
    }
    __syncthreads();

    // ---- Windowed overlap-add epilogue: 4 consecutive k/thread, 16 segs/thread ----
    {
        const int lt = tid & 63;
        const int h  = tid >> 6;                       // segment quarter 0..3
        const int k0 = 4 * lt;                         // 0..252
        const bool lo = (lt < 32);                     // warp-uniform
        float wA[4], wB[4];
        #pragma unroll
        for (int d = 0; d < 4; d++) {
            int k = k0 + d;
            wA[d] = __ldg(&g_win[k]) * (lo ? -1.0f : 1.0f);
            wB[d] = __ldg(&g_win[k + 256]);
        }
        const int aOff = lo ? (124 - k0) : (k0 - 128); // word offset of zA quad
        const int bOff = lo ? (k0 + 128) : (380 - k0); // word offset of zB quad
        float* ob = out + (size_t)b * LOUT + k0;

        #pragma unroll 4
        for (int i = 0; i < NSEG / 4; i++) {
            int ci = 16 * h + i;                       // zB col; zA col = ci+1
            int s  = s0 + ci;
            if (s <= 4096) {
                float4 a4 = *reinterpret_cast<const float4*>(sm + (ci + 1) * DSTR + aOff);
                float4 b4 = *reinterpret_cast<const float4*>(sm + ci * DSTR + bOff);
                float av[4], bv[4];
                if (lo) { av[0]=a4.w; av[1]=a4.z; av[2]=a4.y; av[3]=a4.x;
                          bv[0]=b4.x; bv[1]=b4.y; bv[2]=b4.z; bv[3]=b4.w; }
                else    { av[0]=a4.x; av[1]=a4.y; av[2]=a4.z; av[3]=a4.w;
                          bv[0]=b4.w; bv[1]=b4.z; bv[2]=b4.y; bv[3]=b4.x; }
                float4 o;
                o.x = wA[0] * av[0] + wB[0] * bv[0];
                o.y = wA[1] * av[1] + wB[1] * bv[1];
                o.z = wA[2] * av[2] + wB[2] * bv[2];
                o.w = wA[3] * av[3] + wB[3] * bv[3];
                *reinterpret_cast<float4*>(ob + (size_t)s * 256) = o;
            }
        }
    }
}

extern "C" void kernel_launch(void* const* d_in, const int* in_sizes, int n_in,
                              void* d_out, int out_size)
{
    const float* spec    = (const float*)d_in[0];   // [16,1,256,4096]
    const float* kernels = (const float*)d_in[1];   // [512,256]
    float* out = (float*)d_out;                     // [16,1048832]

    prep_kernel<<<32, 256>>>(kernels);              // 8192 threads

    cudaFuncSetAttribute(imdct_main_kernel,
                         cudaFuncAttributeMaxDynamicSharedMemorySize, SMBYTES);
    dim3 grid((4097 + NSEG - 1) / NSEG, 16);        // (65, 16)
    imdct_main_kernel<<<grid, 256, SMBYTES>>>(spec, out);
}

// round 10
// speedup vs baseline: 1.5581x; 1.5581x over previous
#include <cuda_runtime.h>
#include <cstdint>
#include <math.h>

// IMDCT, round 10: symmetry-halved + Cooley-Tukey two-stage (f = 16*f1 + f0).
//
//   z_col[t] = sum_f kr[t][f]*S[f],  kr[t][f] = kernels[128+t][f]/(128*win(128+t))
//            = sum_u W2[t][u] * PQ[u][tau],  tau = t & 31
//   PQ[f0][tau]    = P = sum_f1 S[16f1+f0]*C1[tau][f1]   (u = f0)
//   PQ[16+f0][tau] = Q = sum_f1 S[16f1+f0]*S1[tau][f1]   (u = 16+f0)
//   W2[t][f0]    = kr[t][f0]
//   W2[t][16+f0] = -(-1)^t * kr[t][255-f0]   ( = -sin-part, from INPUT kernels )
//   C1[tau][f1] = cos(pi*(2*tau+513)*f1/32), S1 = sin(...)
// Output: out[b, s*256+k] = win[k]*(k<128 ? -z_s[127-k] : z_s[k-128])
//                         + win[k+256]*(k<128 ? z_{s-1}[k+128] : z_{s-1}[383-k])
//
// Block = 64 threads (2 warps), NSEG=16 segments, 18 spec cols. Per colpair chunk:
// stage-1 (warp w does col 2j+w; lane = tau; S broadcast LDS.128, C1/S1 in regs),
// sync, stage-2 (4 t-rows/thread, 32-u dot from PQ smem + W2 LDG), z written into
// the now-dead smT columns (Dt overlay). Epilogue = windowed overlap-add.

#define NFREQ    256
#define TFRAMES  4096
#define NSEG     16
#define NCOLS    18
#define TSTR     260        // smT/Dt per-col stride (words); 1040B, 16B-aligned
#define PQSTR    66         // PQ per-tau stride (words); even -> phase-clean b64
#define PQBUF    (32 * PQSTR)
#define SMWORDS  (NCOLS * TSTR)
#define SMBYTES  ((SMWORDS + 2 * PQBUF) * 4)   // 35,616 B
#define LOUT     1048832

#define FMA2(acc, a, v) \
    asm("fma.rn.f32x2 %0, %1, %2, %0;" : "+l"(acc) : "l"(a), "l"(v))
#define PACK2(dst, x) \
    asm("mov.b64 %0, {%1, %1};" : "=l"(dst) : "r"(__float_as_uint(x)))

__device__ float4 g_w2[32 * 64];    // [u][tid]: {W2[t], W2[t+64], W2[t+128], W2[t+192]}
__device__ float  g_c1s1[32 * 32];  // [tau][j]: j<16 -> C1[tau][j], j>=16 -> S1[tau][j-16]
__device__ float  g_win[512];

__global__ void prep_kernel(const float* __restrict__ kernels)
{
    int idx = blockIdx.x * blockDim.x + threadIdx.x;   // 4096 threads
    if (idx < 2048) {                                  // g_w2
        int u = idx >> 6, tid = idx & 63;
        float r[4];
        #pragma unroll
        for (int m = 0; m < 4; m++) {
            int t = tid + 64 * m;
            double wn = sin(M_PI * (double)(2 * (128 + t) + 1) / 1024.0);
            double sc = 1.0 / (128.0 * wn);
            if (u < 16)
                r[m] = (float)((double)kernels[(128 + t) * 256 + u] * sc);
            else {
                float sgn = (t & 1) ? 1.0f : -1.0f;    // -(-1)^t
                r[m] = sgn * (float)((double)kernels[(128 + t) * 256 + (255 - (u - 16))] * sc);
            }
        }
        g_w2[u * 64 + tid] = make_float4(r[0], r[1], r[2], r[3]);
    } else if (idx < 3072) {                           // g_c1s1
        int i = idx - 2048;
        int tau = i >> 5, j = i & 31;
        int f1 = j & 15;
        double ang = M_PI * (double)(2 * tau + 513) * (double)f1 / 32.0;
        g_c1s1[tau * 32 + j] = (float)((j < 16) ? cos(ang) : sin(ang));
    } else if (idx < 3584) {                           // g_win
        int t = idx - 3072;
        g_win[t] = (float)sin(M_PI * (double)(2 * t + 1) / 1024.0);
    }
}

__global__ __launch_bounds__(64, 6)
void imdct_main_kernel(const float* __restrict__ spec, float* __restrict__ out)
{
    extern __shared__ float sm[];                      // smT [18][260] then PQ [2][32][66]
    const int tid  = threadIdx.x;                      // 0..63
    const int lane = tid & 31;                         // tau
    const int w    = tid >> 5;                         // warp 0/1
    const int b    = blockIdx.y;
    const int s0   = blockIdx.x * NSEG;

    // ---- Stage spec TRANSPOSED: smT[c][f] = spec[b][f][s0-1+c], zero-fill edges ----
    const float* specB = spec + (size_t)b * NFREQ * TFRAMES;
    for (int i = tid; i < NFREQ * NCOLS; i += 64) {
        int f = i / NCOLS;
        int c = i - f * NCOLS;
        int cg = s0 - 1 + c;
        float v = (cg >= 0 && cg < TFRAMES) ? __ldg(&specB[(size_t)f * TFRAMES + cg]) : 0.0f;
        sm[c * TSTR + f] = v;
    }

    // ---- Per-lane stage-1 basis in registers ----
    float c1[16], s1[16];
    {
        const float4* cp = (const float4*)(g_c1s1 + lane * 32);
        #pragma unroll
        for (int q = 0; q < 4; q++) {
            float4 a = __ldg(&cp[q]);
            c1[4*q] = a.x; c1[4*q+1] = a.y; c1[4*q+2] = a.z; c1[4*q+3] = a.w;
        }
        #pragma unroll
        for (int q = 0; q < 4; q++) {
            float4 a = __ldg(&cp[4 + q]);
            s1[4*q] = a.x; s1[4*q+1] = a.y; s1[4*q+2] = a.z; s1[4*q+3] = a.w;
        }
    }

    const uint32_t smb = (uint32_t)__cvta_generic_to_shared(sm);
    const uint32_t pqb = smb + SMWORDS * 4;
    const float4* __restrict__ w2p = ((const float4*)g_w2) + tid;   // [u*64 + tid]

    __syncthreads();

    #pragma unroll 1
    for (int j = 0; j < 9; j++) {
        // ======== stage 1: this warp reduces f1 for column 2j+w ========
        unsigned long long aP[8], aQ[8];
        #pragma unroll
        for (int p = 0; p < 8; p++) { aP[p] = 0ull; aQ[p] = 0ull; }

        const uint32_t colb = smb + (uint32_t)((2 * j + w) * TSTR * 4);
        #pragma unroll
        for (int f1 = 0; f1 < 16; f1++) {
            unsigned long long v[8];                   // S[16f1+0..15] as 8 f0-pairs
            #pragma unroll
            for (int q = 0; q < 4; q++)
                asm volatile("ld.shared.v2.b64 {%0, %1}, [%2];"
                             : "=l"(v[2*q]), "=l"(v[2*q+1]) : "r"(colb + f1 * 64 + q * 16));
            unsigned long long cc, ss;
            PACK2(cc, c1[f1]); PACK2(ss, s1[f1]);
            #pragma unroll
            for (int p = 0; p < 8; p++) FMA2(aP[p], cc, v[p]);
            #pragma unroll
            for (int p = 0; p < 8; p++) FMA2(aQ[p], ss, v[p]);
        }
        // store PQ: word addr = tau*66 + 2u + w  (buffer j&1)
        {
            uint32_t pqw = pqb + (uint32_t)(((j & 1) * PQBUF + lane * PQSTR + w) * 4);
            #pragma unroll
            for (int p = 0; p < 8; p++) {              // P: u=2p,2p+1 ; Q: u=16+2p,17+2p
                uint32_t pl = (uint32_t)aP[p], ph = (uint32_t)(aP[p] >> 32);
                uint32_t ql = (uint32_t)aQ[p], qh = (uint32_t)(aQ[p] >> 32);
                asm volatile("st.shared.b32 [%0], %1;" :: "r"(pqw + (4*p)      * 4), "r"(pl));
                asm volatile("st.shared.b32 [%0], %1;" :: "r"(pqw + (4*p + 2)  * 4), "r"(ph));
                asm volatile("st.shared.b32 [%0], %1;" :: "r"(pqw + (32 + 4*p) * 4), "r"(ql));
                asm volatile("st.shared.b32 [%0], %1;" :: "r"(pqw + (34 + 4*p) * 4), "r"(qh));
            }
        }
        __syncthreads();

        // ======== stage 2: z[t=tid+64m] for cols (2j, 2j+1) ========
        unsigned long long z2[4];
        z2[0] = z2[1] = z2[2] = z2[3] = 0ull;
        const uint32_t pqr = pqb + (uint32_t)(((j & 1) * PQBUF + lane * PQSTR) * 4);
        #pragma unroll 8
        for (int u = 0; u < 32; u++) {
            float4 w4 = __ldg(&w2p[u * 64]);
            unsigned long long vq;
            asm volatile("ld.shared.b64 %0, [%1];" : "=l"(vq) : "r"(pqr + u * 8));
            unsigned long long m0, m1, m2, m3;
            PACK2(m0, w4.x); PACK2(m1, w4.y); PACK2(m2, w4.z); PACK2(m3, w4.w);
            FMA2(z2[0], m0, vq);
            FMA2(z2[1], m1, vq);
            FMA2(z2[2], m2, vq);
            FMA2(z2[3], m3, vq);
        }
        // overlay z into the (now dead) smT columns 2j, 2j+1: Dt[c][t]
        #pragma unroll
        for (int m = 0; m < 4; m++) {
            int t = tid + 64 * m;
            sm[(2 * j)     * TSTR + t] = __uint_as_float((uint32_t)z2[m]);
            sm[(2 * j + 1) * TSTR + t] = __uint_as_float((uint32_t)(z2[m] >> 32));
        }
    }
    __syncthreads();

    // ---- Windowed overlap-add epilogue: 4 consecutive k/thread, 16 segs ----
    {
        const int k0 = 4 * tid;                        // 0..252
        const bool lo = (tid < 32);                    // warp-uniform
        float wA[4], wB[4];
        #pragma unroll
        for (int d = 0; d < 4; d++) {
            int k = k0 + d;
            wA[d] = __ldg(&g_win[k]) * (lo ? -1.0f : 1.0f);
            wB[d] = __ldg(&g_win[k + 256]);
        }
        const int aOff = lo ? (124 - k0) : (k0 - 128); // word offset of zA quad
        const int bOff = lo ? (k0 + 128) : (380 - k0); // word offset of zB quad
        float* ob = out + (size_t)b * LOUT + k0;

        #pragma unroll 4
        for (int i = 0; i < NSEG; i++) {
            int s = s0 + i;
            if (s <= 4096) {
                float4 a4 = *reinterpret_cast<const float4*>(sm + (i + 1) * TSTR + aOff);
                float4 b4 = *reinterpret_cast<const float4*>(sm + i * TSTR + bOff);
                float av[4], bv[4];
                if (lo) { av[0]=a4.w; av[1]=a4.z; av[2]=a4.y; av[3]=a4.x;
                          bv[0]=b4.x; bv[1]=b4.y; bv[2]=b4.z; bv[3]=b4.w; }
                else    { av[0]=a4.x; av[1]=a4.y; av[2]=a4.z; av[3]=a4.w;
                          bv[0]=b4.w; bv[1]=b4.z; bv[2]=b4.y; bv[3]=b4.x; }
                float4 o;
                o.x = wA[0] * av[0] + wB[0] * bv[0];
                o.y = wA[1] * av[1] + wB[1] * bv[1];
                o.z = wA[2] * av[2] + wB[2] * bv[2];
                o.w = wA[3] * av[3] + wB[3] * bv[3];
                *reinterpret_cast<float4*>(ob + (size_t)s * 256) = o;
            }
        }
    }
}

extern "C" void kernel_launch(void* const* d_in, const int* in_sizes, int n_in,
                              void* d_out, int out_size)
{
    const float* spec    = (const float*)d_in[0];   // [16,1,256,4096]
    const float* kernels = (const float*)d_in[1];   // [512,256]
    float* out = (float*)d_out;                     // [16,1048832]

    prep_kernel<<<16, 256>>>(kernels);              // 4096 threads

    cudaFuncSetAttribute(imdct_main_kernel,
                         cudaFuncAttributeMaxDynamicSharedMemorySize, SMBYTES);
    dim3 grid((4097 + NSEG - 1) / NSEG, 16);        // (257, 16)
    imdct_main_kernel<<<grid, 64, SMBYTES>>>(spec, out);
}